// round 1
// baseline (speedup 1.0000x reference)
#include <cuda_runtime.h>
#include <cstdint>

#define NN 50000
#define NE 800000
#define AF 133
#define BF 14
#define H  128

// ---------------- scratch (device globals; no allocation) ----------------
__device__ float g_h [(size_t)NE * H];   // edge hidden state
__device__ float g_y [(size_t)NE * H];   // edge GEMM output Y = h @ Wh^T
__device__ float g_P [(size_t)NN * H];   // atom @ Wa^T
__device__ float g_S1[(size_t)NN * H];   // segment sums
__device__ float g_S2[(size_t)NN * H];
__device__ float g_S3[(size_t)NN * H];
// transposed weights, packed: WaT[133x128] | WbT[14x128] | WhT[128x128] | WoT[261x128]
__device__ float g_WT[(size_t)(AF + BF + H + (AF + H)) * H];
__device__ int   g_idx64;                // 1 if index arrays are int64, 0 if int32

// ---------------- helpers ----------------
__device__ __forceinline__ int ld_idx(const void* p, long i) {
    if (g_idx64) return (int)__ldg((const long long*)p + i);
    return __ldg((const int*)p + i);
}

__device__ __forceinline__ void red4(float* p, float4 v) {
    asm volatile("red.global.add.v4.f32 [%0], {%1,%2,%3,%4};"
                 :: "l"(p), "f"(v.x), "f"(v.y), "f"(v.z), "f"(v.w) : "memory");
}

// ---------------- detect int32 vs int64 index arrays ----------------
__global__ void detect_idx(const unsigned int* srcw) {
    __shared__ unsigned int s;
    if (threadIdx.x == 0) s = 0;
    __syncthreads();
    // If int64 (values < 2^31), every odd 32-bit word is 0. If int32, these are
    // random node ids — OR over 512 samples is certainly nonzero.
    unsigned int v = srcw[threadIdx.x * 2 + 1] | srcw[2048 + threadIdx.x * 2 + 1];
    atomicOr(&s, v);
    __syncthreads();
    if (threadIdx.x == 0) g_idx64 = (s == 0u) ? 1 : 0;
}

// ---------------- transpose all weights into g_WT ----------------
__global__ void prep_w(const float* __restrict__ Wi, const float* __restrict__ Wh,
                       const float* __restrict__ Wo) {
    int i = blockIdx.x * blockDim.x + threadIdx.x;
    if (i >= (AF + H) * H) return;        // largest region is 261x128
    int j = i & 127, k = i >> 7;
    if (k < AF) g_WT[i]                     = Wi[j * (AF + BF) + k];          // WaT
    if (k < BF) g_WT[AF * H + i]            = Wi[j * (AF + BF) + AF + k];     // WbT
    if (k < H)  g_WT[(AF + BF) * H + i]     = Wh[j * H + k];                  // WhT
    if (k < AF + H) g_WT[(AF + BF + H) * H + i] = Wo[j * (AF + H) + k];       // WoT
}

// ---------------- zero a node buffer [NN, H] ----------------
__global__ void zero_node(float4* p) {
    long i = (long)blockIdx.x * blockDim.x + threadIdx.x;   // grid covers NN*H/4 exactly
    p[i] = make_float4(0.f, 0.f, 0.f, 0.f);
}

// ---------------- node GEMM: out[N,H] = [A0 | A1] @ sW, optional relu --------
// One warp per row; thread owns 4 output cols. W tile cached in dynamic smem.
template<int KD, bool RELU>
__global__ __launch_bounds__(256) void node_gemm(const float* __restrict__ A0,
                                                 const float* __restrict__ A1,
                                                 const float* __restrict__ WT,
                                                 float* __restrict__ out) {
    extern __shared__ float sm[];
    float* sW = sm;              // KD*H
    float* sA = sm + KD * H;     // 8 rows * KD
    for (int i = threadIdx.x; i < KD * H; i += 256) sW[i] = WT[i];
    __syncthreads();
    int warp = threadIdx.x >> 5, lane = threadIdx.x & 31;
    for (int base = blockIdx.x * 8; base < NN; base += gridDim.x * 8) {
        for (int i = threadIdx.x; i < 8 * KD; i += 256) {
            int r = i / KD, c = i % KD;
            float v = (c < AF) ? A0[(size_t)(base + r) * AF + c]
                               : A1[(size_t)(base + r) * H + (c - AF)];
            sA[r * KD + c] = v;
        }
        __syncthreads();
        const float* ar = sA + warp * KD;
        float4 acc = make_float4(0.f, 0.f, 0.f, 0.f);
        #pragma unroll 4
        for (int k = 0; k < KD; k++) {
            float a = ar[k];
            float4 w = *(const float4*)(sW + k * H + lane * 4);
            acc.x += a * w.x; acc.y += a * w.y; acc.z += a * w.z; acc.w += a * w.w;
        }
        if (RELU) {
            acc.x = fmaxf(acc.x, 0.f); acc.y = fmaxf(acc.y, 0.f);
            acc.z = fmaxf(acc.z, 0.f); acc.w = fmaxf(acc.w, 0.f);
        }
        *(float4*)(out + (size_t)(base + warp) * H + lane * 4) = acc;
        __syncthreads();
    }
}

// ---------------- initial edge layer: h = relu(P[src] + bond @ WbT) ----------
__global__ __launch_bounds__(256) void init_edges(const float* __restrict__ bond,
                                                  const void* __restrict__ src,
                                                  float* __restrict__ hout) {
    __shared__ float sWb[BF * H];
    for (int i = threadIdx.x; i < BF * H; i += 256) sWb[i] = g_WT[AF * H + i];
    __syncthreads();
    int warp = threadIdx.x >> 5, lane = threadIdx.x & 31;
    for (long e0 = (long)blockIdx.x * 8; e0 < NE; e0 += (long)gridDim.x * 8) {
        long e = e0 + warp;
        int s = ld_idx(src, e);
        int q = lane * 4;
        float4 acc = *(const float4*)(g_P + (size_t)s * H + q);
        const float* br = bond + e * BF;
        #pragma unroll
        for (int k = 0; k < BF; k++) {
            float b = __ldg(br + k);
            float4 w = *(const float4*)(sWb + k * H + q);
            acc.x += b * w.x; acc.y += b * w.y; acc.z += b * w.z; acc.w += b * w.w;
        }
        acc.x = fmaxf(acc.x, 0.f); acc.y = fmaxf(acc.y, 0.f);
        acc.z = fmaxf(acc.z, 0.f); acc.w = fmaxf(acc.w, 0.f);
        *(float4*)(hout + (size_t)e * H + q) = acc;
    }
}

// ---------------- edge GEMM: Y = A @ WhT, fused scatter-sum S[dst] += Y ------
// Tile 128 edges x 128 cols, K=128, 256 threads, 8x8 micro-tile per thread.
__global__ __launch_bounds__(256, 1) void egemm_scatter(const float* __restrict__ A,
                                                        const float* __restrict__ WTh,
                                                        float* __restrict__ Y,
                                                        float* __restrict__ S,
                                                        const void* __restrict__ dst) {
    extern __shared__ float sm[];
    float* sA = sm;            // [128][128] row-major (rows = edges)
    float* sB = sm + H * H;    // [k][j] = WhT
    long e0 = (long)blockIdx.x * 128;
    {
        const float4* a4 = (const float4*)(A + (size_t)e0 * H);
        float4* s4 = (float4*)sA;
        for (int i = threadIdx.x; i < H * H / 4; i += 256) s4[i] = a4[i];
        const float4* b4 = (const float4*)WTh;
        float4* t4 = (float4*)sB;
        for (int i = threadIdx.x; i < H * H / 4; i += 256) t4[i] = b4[i];
    }
    __syncthreads();
    int tx = threadIdx.x & 15, ty = threadIdx.x >> 4;
    float acc[8][8];
    #pragma unroll
    for (int i = 0; i < 8; i++)
        #pragma unroll
        for (int j = 0; j < 8; j++) acc[i][j] = 0.f;

    const float* pa = sA + ty * 8 * H;
    const float* pb = sB + tx * 8;
    #pragma unroll 4
    for (int k = 0; k < H; k++) {
        float4 b0 = *(const float4*)(pb + k * H);
        float4 b1 = *(const float4*)(pb + k * H + 4);
        float b[8] = {b0.x, b0.y, b0.z, b0.w, b1.x, b1.y, b1.z, b1.w};
        float a[8];
        #pragma unroll
        for (int i = 0; i < 8; i++) a[i] = pa[i * H + k];
        #pragma unroll
        for (int i = 0; i < 8; i++)
            #pragma unroll
            for (int j = 0; j < 8; j++) acc[i][j] += a[i] * b[j];
    }
    #pragma unroll
    for (int i = 0; i < 8; i++) {
        long e = e0 + ty * 8 + i;
        float4 v0 = make_float4(acc[i][0], acc[i][1], acc[i][2], acc[i][3]);
        float4 v1 = make_float4(acc[i][4], acc[i][5], acc[i][6], acc[i][7]);
        float* yp = Y + (size_t)e * H + tx * 8;
        *(float4*)yp = v0;
        *(float4*)(yp + 4) = v1;
        int d = ld_idx(dst, e);
        float* sp = S + (size_t)d * H + tx * 8;
        red4(sp, v0);
        red4(sp + 4, v1);
    }
}

// ------- combine: h = relu(S[src] - Y[rev]); optional fused Snext[dst] += h --
__global__ __launch_bounds__(256) void combine(const float* __restrict__ S,
                                               const float* __restrict__ Yv,
                                               const void* __restrict__ src,
                                               const void* __restrict__ rev,
                                               float* __restrict__ hout,
                                               float* __restrict__ Snext,
                                               const void* __restrict__ dst) {
    long g = (long)blockIdx.x * 256 + threadIdx.x;   // one warp per edge (32 thr * 4 cols)
    long e = g >> 5;
    if (e >= NE) return;
    int q = (int)(g & 31) * 4;
    int s = ld_idx(src, e);
    long r = ld_idx(rev, e);
    float4 sv = *(const float4*)(S + (size_t)s * H + q);
    float4 yv = *(const float4*)(Yv + (size_t)r * H + q);
    float4 h;
    h.x = fmaxf(sv.x - yv.x, 0.f);
    h.y = fmaxf(sv.y - yv.y, 0.f);
    h.z = fmaxf(sv.z - yv.z, 0.f);
    h.w = fmaxf(sv.w - yv.w, 0.f);
    *(float4*)(hout + (size_t)e * H + q) = h;
    if (Snext) {
        int d = ld_idx(dst, e);
        red4(Snext + (size_t)d * H + q, h);
    }
}

// ---------------- launcher ----------------
extern "C" void kernel_launch(void* const* d_in, const int* in_sizes, int n_in,
                              void* d_out, int out_size) {
    const float* atom = (const float*)d_in[0];
    const float* bond = (const float*)d_in[1];
    const float* Wi   = (const float*)d_in[2];
    const float* Wh   = (const float*)d_in[3];
    const float* Wo   = (const float*)d_in[4];
    const void*  src  = d_in[5];
    const void*  dst  = d_in[6];
    const void*  rev  = d_in[7];
    float* out = (float*)d_out;

    float *h, *y, *P, *S1, *S2, *S3, *WT;
    cudaGetSymbolAddress((void**)&h,  g_h);
    cudaGetSymbolAddress((void**)&y,  g_y);
    cudaGetSymbolAddress((void**)&P,  g_P);
    cudaGetSymbolAddress((void**)&S1, g_S1);
    cudaGetSymbolAddress((void**)&S2, g_S2);
    cudaGetSymbolAddress((void**)&S3, g_S3);
    cudaGetSymbolAddress((void**)&WT, g_WT);
    const float* WhT = WT + (AF + BF) * H;
    const float* WoT = WT + (AF + BF + H) * H;

    const int smemG = 2 * H * H * 4;                              // 128 KB
    const int smemP = (AF * H + 8 * AF) * 4;                      // ~72 KB
    const int smemO = ((AF + H) * H + 8 * (AF + H)) * 4;          // ~142 KB
    cudaFuncSetAttribute(egemm_scatter,        cudaFuncAttributeMaxDynamicSharedMemorySize, smemG);
    cudaFuncSetAttribute(node_gemm<AF, false>, cudaFuncAttributeMaxDynamicSharedMemorySize, smemP);
    cudaFuncSetAttribute(node_gemm<AF + H, true>, cudaFuncAttributeMaxDynamicSharedMemorySize, smemO);

    detect_idx<<<1, 256>>>((const unsigned int*)src);
    prep_w<<<((AF + H) * H + 255) / 256, 256>>>(Wi, Wh, Wo);
    zero_node<<<NN * H / 4 / 256, 256>>>((float4*)S1);
    zero_node<<<NN * H / 4 / 256, 256>>>((float4*)S2);
    zero_node<<<NN * H / 4 / 256, 256>>>((float4*)S3);

    // P = atom @ Wa^T (no relu)
    node_gemm<AF, false><<<296, 256, smemP>>>(atom, nullptr, WT, P);
    // h0 = relu(P[src] + bond @ Wb^T)
    init_edges<<<2048, 256>>>(bond, src, h);

    // iteration 1: Y = h @ Wh^T, S1 += scatter(Y); h = relu(S1[src] - Y[rev])
    egemm_scatter<<<NE / 128, 256, smemG>>>(h, WhT, y, S1, dst);
    combine<<<NE * 32 / 256, 256>>>(S1, y, src, rev, h, nullptr, nullptr);

    // iteration 2: Y = h @ Wh^T, S2 += scatter(Y); h = relu(S2[src] - Y[rev]), S3 += scatter(h)
    egemm_scatter<<<NE / 128, 256, smemG>>>(h, WhT, y, S2, dst);
    combine<<<NE * 32 / 256, 256>>>(S2, y, src, rev, h, S3, dst);

    // out = relu([atom | S3] @ Wo^T)
    node_gemm<AF + H, true><<<296, 256, smemO>>>(atom, S3, WoT, out);
}

// round 3
// speedup vs baseline: 1.5573x; 1.5573x over previous
#include <cuda_runtime.h>
#include <cuda_bf16.h>
#include <cstdint>

#define NN 50000
#define NE 800000
#define AF 133
#define BF 14
#define H  128
#define SA_STRIDE 136   // padded bf16 smem row stride (272B -> 4-bank rotation)
#define SD_STRIDE 132   // padded fp32 smem row stride for epilogue

// ---------------- scratch (device globals; no allocation) ----------------
__device__ __nv_bfloat16 g_hh[(size_t)NE * H];   // edge hidden, bf16 hi
__device__ __nv_bfloat16 g_hl[(size_t)NE * H];   // edge hidden, bf16 lo
__device__ float g_y1[(size_t)NE * H];           // Y1 = h0 @ Wh^T
__device__ float g_y2[(size_t)NE * H];           // Y2 = h1 @ Wh^T
__device__ float g_P [(size_t)NN * H];           // atom @ Wa^T
__device__ float g_S1[(size_t)NN * H];
__device__ float g_S2[(size_t)NN * H];
__device__ float g_S3[(size_t)NN * H];
// transposed weights for SIMT node GEMMs: WaT[133x128] | WbT[14x128] | pad | WoT[261x128]
__device__ float g_WT[(size_t)(AF + BF + H + (AF + H)) * H];
// Wh split to bf16 hi/lo, plain row-major [n][k]
__device__ __nv_bfloat16 g_Bh[H * H];
__device__ __nv_bfloat16 g_Bl[H * H];
__device__ int   g_idx64;

// ---------------- helpers ----------------
__device__ __forceinline__ int ld_idx(const void* p, long i) {
    if (g_idx64) return (int)__ldg((const long long*)p + i);
    return __ldg((const int*)p + i);
}
__device__ __forceinline__ void red4(float* p, float4 v) {
    asm volatile("red.global.add.v4.f32 [%0], {%1,%2,%3,%4};"
                 :: "l"(p), "f"(v.x), "f"(v.y), "f"(v.z), "f"(v.w) : "memory");
}
__device__ __forceinline__ uint32_t smem_u32(const void* p) {
    uint32_t a;
    asm("{ .reg .u64 t; cvta.to.shared.u64 t, %1; cvt.u32.u64 %0, t; }" : "=r"(a) : "l"(p));
    return a;
}
__device__ __forceinline__ void bsplit(float v, __nv_bfloat16& h, __nv_bfloat16& l) {
    h = __float2bfloat16(v);
    l = __float2bfloat16(v - __bfloat162float(h));
}
__device__ __forceinline__ uint32_t bpack(__nv_bfloat16 a, __nv_bfloat16 b) {
    return ((uint32_t)__bfloat16_as_ushort(b) << 16) | (uint32_t)__bfloat16_as_ushort(a);
}
__device__ __forceinline__ void ldsm_x4(uint32_t (&r)[4], uint32_t addr) {
    asm volatile("ldmatrix.sync.aligned.m8n8.x4.shared.b16 {%0,%1,%2,%3}, [%4];"
                 : "=r"(r[0]), "=r"(r[1]), "=r"(r[2]), "=r"(r[3]) : "r"(addr));
}
__device__ __forceinline__ void ldsm_x2(uint32_t (&r)[2], uint32_t addr) {
    asm volatile("ldmatrix.sync.aligned.m8n8.x2.shared.b16 {%0,%1}, [%2];"
                 : "=r"(r[0]), "=r"(r[1]) : "r"(addr));
}
__device__ __forceinline__ void mma_bf16(float (&d)[4], const uint32_t (&a)[4], const uint32_t (&b)[2]) {
    asm volatile("mma.sync.aligned.m16n8k16.row.col.f32.bf16.bf16.f32 "
                 "{%0,%1,%2,%3}, {%4,%5,%6,%7}, {%8,%9}, {%0,%1,%2,%3};"
                 : "+f"(d[0]), "+f"(d[1]), "+f"(d[2]), "+f"(d[3])
                 : "r"(a[0]), "r"(a[1]), "r"(a[2]), "r"(a[3]), "r"(b[0]), "r"(b[1]));
}

// ---------------- detect int32 vs int64 index arrays ----------------
__global__ void detect_idx(const unsigned int* srcw) {
    __shared__ unsigned int s;
    if (threadIdx.x == 0) s = 0;
    __syncthreads();
    unsigned int v = srcw[threadIdx.x * 2 + 1] | srcw[2048 + threadIdx.x * 2 + 1];
    atomicOr(&s, v);
    __syncthreads();
    if (threadIdx.x == 0) g_idx64 = (s == 0u) ? 1 : 0;
}

// ---------------- weight prep ----------------
__global__ void prep_w(const float* __restrict__ Wi, const float* __restrict__ Wh,
                       const float* __restrict__ Wo) {
    int i = blockIdx.x * blockDim.x + threadIdx.x;
    if (i >= (AF + H) * H) return;
    int j = i & 127, k = i >> 7;
    if (k < AF) g_WT[i]          = Wi[j * (AF + BF) + k];                 // WaT
    if (k < BF) g_WT[AF * H + i] = Wi[j * (AF + BF) + AF + k];            // WbT
    if (k < AF + H) g_WT[(AF + BF + H) * H + i] = Wo[j * (AF + H) + k];   // WoT
    if (i < H * H) {
        __nv_bfloat16 hi, lo; bsplit(Wh[i], hi, lo);
        g_Bh[i] = hi;
        g_Bl[i] = lo;
    }
}

__global__ void zero_node(float4* p) {
    long i = (long)blockIdx.x * blockDim.x + threadIdx.x;
    p[i] = make_float4(0.f, 0.f, 0.f, 0.f);
}

// ---------------- node GEMM (SIMT fp32): out[N,H] = [A0|A1] @ sW ------------
template<int KD, bool RELU>
__global__ __launch_bounds__(256) void node_gemm(const float* __restrict__ A0,
                                                 const float* __restrict__ A1,
                                                 const float* __restrict__ WT,
                                                 float* __restrict__ out) {
    extern __shared__ float sm[];
    float* sW = sm;
    float* sA = sm + KD * H;
    for (int i = threadIdx.x; i < KD * H; i += 256) sW[i] = WT[i];
    __syncthreads();
    int warp = threadIdx.x >> 5, lane = threadIdx.x & 31;
    for (int base = blockIdx.x * 8; base < NN; base += gridDim.x * 8) {
        for (int i = threadIdx.x; i < 8 * KD; i += 256) {
            int r = i / KD, c = i % KD;
            float v = (c < AF) ? A0[(size_t)(base + r) * AF + c]
                               : A1[(size_t)(base + r) * H + (c - AF)];
            sA[r * KD + c] = v;
        }
        __syncthreads();
        const float* ar = sA + warp * KD;
        float4 acc = make_float4(0.f, 0.f, 0.f, 0.f);
        #pragma unroll 4
        for (int k = 0; k < KD; k++) {
            float a = ar[k];
            float4 w = *(const float4*)(sW + k * H + lane * 4);
            acc.x += a * w.x; acc.y += a * w.y; acc.z += a * w.z; acc.w += a * w.w;
        }
        if (RELU) {
            acc.x = fmaxf(acc.x, 0.f); acc.y = fmaxf(acc.y, 0.f);
            acc.z = fmaxf(acc.z, 0.f); acc.w = fmaxf(acc.w, 0.f);
        }
        *(float4*)(out + (size_t)(base + warp) * H + lane * 4) = acc;
        __syncthreads();
    }
}

// ---- initial edge layer: h0 = relu(P[src] + bond @ WbT), stored bf16 hi/lo -
__global__ __launch_bounds__(256) void init_edges(const float* __restrict__ bond,
                                                  const void* __restrict__ src) {
    __shared__ float sWb[BF * H];
    for (int i = threadIdx.x; i < BF * H; i += 256) sWb[i] = g_WT[AF * H + i];
    __syncthreads();
    int warp = threadIdx.x >> 5, lane = threadIdx.x & 31;
    for (long e0 = (long)blockIdx.x * 8; e0 < NE; e0 += (long)gridDim.x * 8) {
        long e = e0 + warp;
        int s = ld_idx(src, e);
        int q = lane * 4;
        float4 acc = *(const float4*)(g_P + (size_t)s * H + q);
        const float* br = bond + e * BF;
        #pragma unroll
        for (int k = 0; k < BF; k++) {
            float b = __ldg(br + k);
            float4 w = *(const float4*)(sWb + k * H + q);
            acc.x += b * w.x; acc.y += b * w.y; acc.z += b * w.z; acc.w += b * w.w;
        }
        acc.x = fmaxf(acc.x, 0.f); acc.y = fmaxf(acc.y, 0.f);
        acc.z = fmaxf(acc.z, 0.f); acc.w = fmaxf(acc.w, 0.f);
        __nv_bfloat16 h0,h1,h2,h3,l0,l1,l2,l3;
        bsplit(acc.x,h0,l0); bsplit(acc.y,h1,l1); bsplit(acc.z,h2,l2); bsplit(acc.w,h3,l3);
        size_t off = (size_t)e * H + q;
        *(uint2*)(g_hh + off) = make_uint2(bpack(h0,h1), bpack(h2,h3));
        *(uint2*)(g_hl + off) = make_uint2(bpack(l0,l1), bpack(l2,l3));
    }
}

// ---------------- tensor-core edge GEMM via mma.sync ------------------------
// Per CTA: 128-edge tile. D = Ah@Bh^T + Al@Bh^T + Ah@Bl^T (fp32 acc).
// MODE 0: A from g_hh/g_hl. MODE 1: A = relu(Sprev[src]-Yprev[rev]) split on the fly.
// Epilogue: D through smem -> coalesced Y write + red.add scatter into Sout[dst].
template<int MODE>
__global__ __launch_bounds__(512, 1) void egemm_mma(
    const __nv_bfloat16* __restrict__ Ah, const __nv_bfloat16* __restrict__ Al,
    const float* __restrict__ Sprev, const float* __restrict__ Yprev,
    const void* __restrict__ srcp, const void* __restrict__ revp,
    const uint4* __restrict__ Bh4, const uint4* __restrict__ Bl4,
    float* __restrict__ Yout, float* __restrict__ Sout,
    const void* __restrict__ dstp)
{
    extern __shared__ __align__(16) char dyn[];
    __nv_bfloat16* sAh = (__nv_bfloat16*)dyn;
    __nv_bfloat16* sAl = sAh + 128 * SA_STRIDE;
    __nv_bfloat16* sBh = sAl + 128 * SA_STRIDE;
    __nv_bfloat16* sBl = sBh + 128 * SA_STRIDE;

    int tid = threadIdx.x, lane = tid & 31, wid = tid >> 5;
    long e0 = (long)blockIdx.x * 128;

    // ---- B (hi/lo) into padded smem
    #pragma unroll
    for (int it = 0; it < 4; it++) {
        int i = tid + it * 512;                 // 2048 chunks of 16B per matrix
        int r = i >> 4, c = i & 15;
        *(uint4*)(sBh + r * SA_STRIDE + c * 8) = __ldg(Bh4 + i);
        *(uint4*)(sBl + r * SA_STRIDE + c * 8) = __ldg(Bl4 + i);
    }

    // ---- build A rows (thread t: row t>>2, 32-col chunk t&3)
    {
        int row = tid >> 2, q = tid & 3;
        long e = e0 + row;
        if (MODE == 0) {
            const uint4* ph = (const uint4*)(Ah + (size_t)e * H + q * 32);
            const uint4* pl = (const uint4*)(Al + (size_t)e * H + q * 32);
            uint4* dh = (uint4*)(sAh + row * SA_STRIDE + q * 32);
            uint4* dl = (uint4*)(sAl + row * SA_STRIDE + q * 32);
            #pragma unroll
            for (int i = 0; i < 4; i++) dh[i] = __ldg(ph + i);
            #pragma unroll
            for (int i = 0; i < 4; i++) dl[i] = __ldg(pl + i);
        } else {
            int  s = ld_idx(srcp, e);
            long r = ld_idx(revp, e);
            const float4* ps = (const float4*)(Sprev + (size_t)s * H + q * 32);
            const float4* py = (const float4*)(Yprev + (size_t)r * H + q * 32);
            uint2* dh = (uint2*)(sAh + row * SA_STRIDE + q * 32);
            uint2* dl = (uint2*)(sAl + row * SA_STRIDE + q * 32);
            #pragma unroll
            for (int i = 0; i < 8; i++) {
                float4 sv = __ldg(ps + i), yv = __ldg(py + i);
                float4 hv;
                hv.x = fmaxf(sv.x - yv.x, 0.f); hv.y = fmaxf(sv.y - yv.y, 0.f);
                hv.z = fmaxf(sv.z - yv.z, 0.f); hv.w = fmaxf(sv.w - yv.w, 0.f);
                __nv_bfloat16 h0,h1,h2,h3,l0,l1,l2,l3;
                bsplit(hv.x,h0,l0); bsplit(hv.y,h1,l1); bsplit(hv.z,h2,l2); bsplit(hv.w,h3,l3);
                dh[i] = make_uint2(bpack(h0,h1), bpack(h2,h3));
                dl[i] = make_uint2(bpack(l0,l1), bpack(l2,l3));
            }
        }
    }
    __syncthreads();

    // ---- mainloop: warp grid 4 (m) x 4 (n); warp tile 32x32 = 2x4 m16n8k16
    int wm = (wid >> 2) * 32;
    int wn = (wid & 3) * 32;
    float acc[2][4][4];
    #pragma unroll
    for (int mt = 0; mt < 2; mt++)
        #pragma unroll
        for (int nt = 0; nt < 4; nt++)
            #pragma unroll
            for (int i = 0; i < 4; i++) acc[mt][nt][i] = 0.f;

    #pragma unroll
    for (int pass = 0; pass < 3; pass++) {
        uint32_t abase = smem_u32(pass == 1 ? sAl : sAh);
        uint32_t bbase = smem_u32(pass == 2 ? sBl : sBh);
        uint32_t aAddr0 = abase + ((uint32_t)(wm + (lane & 15)) * SA_STRIDE + (lane >> 4) * 8) * 2;
        uint32_t aAddr1 = aAddr0 + 16 * SA_STRIDE * 2;
        uint32_t bAddr  = bbase + ((uint32_t)(wn + (lane & 7)) * SA_STRIDE + ((lane >> 3) & 1) * 8) * 2;
        #pragma unroll
        for (int ks = 0; ks < 8; ks++) {
            uint32_t koff = (uint32_t)ks * 32;    // 16 bf16 = 32B
            uint32_t a0[4], a1[4];
            ldsm_x4(a0, aAddr0 + koff);
            ldsm_x4(a1, aAddr1 + koff);
            uint32_t b[4][2];
            #pragma unroll
            for (int nt = 0; nt < 4; nt++)
                ldsm_x2(b[nt], bAddr + (uint32_t)nt * 8 * SA_STRIDE * 2 + koff);
            #pragma unroll
            for (int nt = 0; nt < 4; nt++) {
                mma_bf16(acc[0][nt], a0, b[nt]);
                mma_bf16(acc[1][nt], a1, b[nt]);
            }
        }
    }
    __syncthreads();            // all warps done reading sA before D overwrites it

    // ---- D fragments -> smem fp32 tile (stride 132)
    float* sD = (float*)dyn;
    {
        int g = lane >> 2, t2 = (lane & 3) * 2;
        #pragma unroll
        for (int mt = 0; mt < 2; mt++)
            #pragma unroll
            for (int nt = 0; nt < 4; nt++) {
                int r0 = wm + mt * 16 + g, c0 = wn + nt * 8 + t2;
                *(float2*)(sD + r0 * SD_STRIDE + c0)       = make_float2(acc[mt][nt][0], acc[mt][nt][1]);
                *(float2*)(sD + (r0 + 8) * SD_STRIDE + c0) = make_float2(acc[mt][nt][2], acc[mt][nt][3]);
            }
    }
    __syncthreads();

    // ---- epilogue: thread t: row t&127, 32-col chunk t>>7
    {
        int row = tid & 127, q = tid >> 7;
        long e = e0 + row;
        int d = ld_idx(dstp, e);
        const float4* sp = (const float4*)(sD + row * SD_STRIDE + q * 32);
        float* yrow = Yout + (size_t)e * H + q * 32;
        float* srow = Sout + (size_t)d * H + q * 32;
        #pragma unroll
        for (int i = 0; i < 8; i++) {
            float4 v = sp[i];
            *(float4*)(yrow + i * 4) = v;
            red4(srow + i * 4, v);
        }
    }
}

// ------- final combine: scatter relu(S2[src] - Y2[rev]) into S3[dst] --------
__global__ __launch_bounds__(256) void combine2(const float* __restrict__ S,
                                                const float* __restrict__ Yv,
                                                const void* __restrict__ src,
                                                const void* __restrict__ rev,
                                                float* __restrict__ S3,
                                                const void* __restrict__ dst) {
    long g = (long)blockIdx.x * 256 + threadIdx.x;
    long e = g >> 5;
    if (e >= NE) return;
    int q = (int)(g & 31) * 4;
    int s = ld_idx(src, e);
    long r = ld_idx(rev, e);
    int d = ld_idx(dst, e);
    float4 sv = *(const float4*)(S + (size_t)s * H + q);
    float4 yv = *(const float4*)(Yv + (size_t)r * H + q);
    float4 h;
    h.x = fmaxf(sv.x - yv.x, 0.f);
    h.y = fmaxf(sv.y - yv.y, 0.f);
    h.z = fmaxf(sv.z - yv.z, 0.f);
    h.w = fmaxf(sv.w - yv.w, 0.f);
    red4(S3 + (size_t)d * H + q, h);
}

// ---------------- launcher ----------------
extern "C" void kernel_launch(void* const* d_in, const int* in_sizes, int n_in,
                              void* d_out, int out_size) {
    const float* atom = (const float*)d_in[0];
    const float* bond = (const float*)d_in[1];
    const float* Wi   = (const float*)d_in[2];
    const float* Wh   = (const float*)d_in[3];
    const float* Wo   = (const float*)d_in[4];
    const void*  src  = d_in[5];
    const void*  dst  = d_in[6];
    const void*  rev  = d_in[7];
    float* out = (float*)d_out;

    __nv_bfloat16 *hh, *hl, *Bh, *Bl;
    float *y1, *y2, *P, *S1, *S2, *S3, *WT;
    cudaGetSymbolAddress((void**)&hh, g_hh);
    cudaGetSymbolAddress((void**)&hl, g_hl);
    cudaGetSymbolAddress((void**)&Bh, g_Bh);
    cudaGetSymbolAddress((void**)&Bl, g_Bl);
    cudaGetSymbolAddress((void**)&y1, g_y1);
    cudaGetSymbolAddress((void**)&y2, g_y2);
    cudaGetSymbolAddress((void**)&P,  g_P);
    cudaGetSymbolAddress((void**)&S1, g_S1);
    cudaGetSymbolAddress((void**)&S2, g_S2);
    cudaGetSymbolAddress((void**)&S3, g_S3);
    cudaGetSymbolAddress((void**)&WT, g_WT);
    const float* WoT = WT + (AF + BF + H) * H;

    const int smemP = (AF * H + 8 * AF) * 4;
    const int smemO = ((AF + H) * H + 8 * (AF + H)) * 4;
    const int smemG = 4 * 128 * SA_STRIDE * 2;   // 139264 B
    cudaFuncSetAttribute(node_gemm<AF, false>,    cudaFuncAttributeMaxDynamicSharedMemorySize, smemP);
    cudaFuncSetAttribute(node_gemm<AF + H, true>, cudaFuncAttributeMaxDynamicSharedMemorySize, smemO);
    cudaFuncSetAttribute(egemm_mma<0>, cudaFuncAttributeMaxDynamicSharedMemorySize, smemG);
    cudaFuncSetAttribute(egemm_mma<1>, cudaFuncAttributeMaxDynamicSharedMemorySize, smemG);

    detect_idx<<<1, 256>>>((const unsigned int*)src);
    prep_w<<<((AF + H) * H + 255) / 256, 256>>>(Wi, Wh, Wo);
    zero_node<<<NN * H / 4 / 256, 256>>>((float4*)S1);
    zero_node<<<NN * H / 4 / 256, 256>>>((float4*)S2);
    zero_node<<<NN * H / 4 / 256, 256>>>((float4*)S3);

    // P = atom @ Wa^T
    node_gemm<AF, false><<<296, 256, smemP>>>(atom, nullptr, WT, P);
    // h0 (bf16 hi/lo) = relu(P[src] + bond @ Wb^T)
    init_edges<<<2048, 256>>>(bond, src);

    // iter 1: Y1 = h0 @ Wh^T (mma.sync, 3-pass bf16), scatter S1
    egemm_mma<0><<<NE / 128, 512, smemG>>>(hh, hl, nullptr, nullptr, nullptr, nullptr,
                                           (const uint4*)Bh, (const uint4*)Bl, y1, S1, dst);
    // iter 2: rows = relu(S1[src] - Y1[rev]) built in prologue; Y2, scatter S2
    egemm_mma<1><<<NE / 128, 512, smemG>>>(nullptr, nullptr, S1, y1, src, rev,
                                           (const uint4*)Bh, (const uint4*)Bl, y2, S2, dst);
    // final combine: scatter relu(S2[src] - Y2[rev]) into S3
    combine2<<<NE * 32 / 256, 256>>>(S2, y2, src, rev, S3, dst);

    // out = relu([atom | S3] @ Wo^T)
    node_gemm<AF + H, true><<<296, 256, smemO>>>(atom, S3, WoT, out);
}